// round 11
// baseline (speedup 1.0000x reference)
#include <cuda_runtime.h>

#define DEV_INLINE __device__ __forceinline__
typedef unsigned long long ull;

constexpr int C  = 8;
constexpr int K  = 64;
constexpr int NN = 2048;

// ---- per-(c,k) repacked blob layout (floats) ----
constexpr int BLOB = 5632;               // 22528 B = 1408 x 16B chunks; /64 thr = 22
constexpr int W1S = 0;                   // [64][20] stride-padded, cols 0..15 valid
constexpr int W1T = 1280;
constexpr int W2S = 2560;                // transposed [i][r], stride 20
constexpr int W2T = 3840;
constexpr int B1S = 5120, B1T = 5184;
constexpr int B2S = 5248, B2T = 5264;    // passive order
constexpr int ANE = 5280;                // [act 16 | pas 16] exp(-s)
constexpr int ANF = 5312;                // [act 16 | pas 16] -t*exp(-s)
constexpr int ASUM = 5344;

__device__ float g_blob[C * K * BLOB];
__device__ float g_Bm[C * NN];
__device__ float g_Sn[C * C];

// ---------- packed f32x2 helpers ----------
DEV_INLINE ull pack2(float lo, float hi) {
    ull r; asm("mov.b64 %0, {%1,%2};" : "=l"(r) : "f"(lo), "f"(hi)); return r;
}
DEV_INLINE void unpack2(ull v, float& lo, float& hi) {
    asm("mov.b64 {%0,%1}, %2;" : "=f"(lo), "=f"(hi) : "l"(v));
}
DEV_INLINE ull ffma2(ull a, ull b, ull c) {
    ull d; asm("fma.rn.f32x2 %0, %1, %2, %3;" : "=l"(d) : "l"(a), "l"(b), "l"(c)); return d;
}
DEV_INLINE ull add2(ull a, ull b) {
    ull d; asm("add.rn.f32x2 %0, %1, %2;" : "=l"(d) : "l"(a), "l"(b)); return d;
}
DEV_INLINE ull mul2(ull a, ull b) {
    ull d; asm("mul.rn.f32x2 %0, %1, %2;" : "=l"(d) : "l"(a), "l"(b)); return d;
}
DEV_INLINE ull neg2(ull a) { return a ^ 0x8000000080000000ULL; }

// ---------- cp.async staging (64-thread block: 22 chunks each) ----------
DEV_INLINE void stage(float* sdst, const float* gsrc, int tid) {
    unsigned sa = (unsigned)__cvta_generic_to_shared(sdst);
    #pragma unroll
    for (int i = 0; i < 22; i++) {
        int ch = tid + i * 64;
        asm volatile("cp.async.cg.shared.global [%0], [%1], 16;"
                     :: "r"(sa + ch * 16), "l"(gsrc + ch * 4));
    }
    asm volatile("cp.async.commit_group;");
}
DEV_INLINE void wait_stage() {
    asm volatile("cp.async.wait_group 0;" ::: "memory");
}

// ---------- repack: gather/compact/transpose weights once ----------
__global__ void __launch_bounds__(128)
repack_kernel(const float* __restrict__ sW1, const float* __restrict__ sb1,
              const float* __restrict__ sW2, const float* __restrict__ sb2,
              const float* __restrict__ tW1, const float* __restrict__ tb1,
              const float* __restrict__ tW2, const float* __restrict__ tb2,
              const float* __restrict__ anS, const float* __restrict__ anT)
{
    const int ck = blockIdx.x;          // c*64+k
    const int k = ck & 63;
    const int A = k & 1, PO = 1 - A;    // active / passive parity
    float* B = g_blob + (size_t)ck * BLOB;
    const int tid = threadIdx.x;
    const size_t wo = (size_t)ck * 2048;

    for (int idx = tid; idx < 1024; idx += 128) {
        int i = idx >> 4, j = idx & 15;
        B[W1S + i * 20 + j] = sW1[wo + i * 32 + 2 * j + A];
        B[W1T + i * 20 + j] = tW1[wo + i * 32 + 2 * j + A];
        B[W2S + i * 20 + j] = sW2[wo + (2 * j + PO) * 64 + i];
        B[W2T + i * 20 + j] = tW2[wo + (2 * j + PO) * 64 + i];
    }
    if (tid < 64) {
        B[B1S + tid] = sb1[ck * 64 + tid];
        B[B1T + tid] = tb1[ck * 64 + tid];
    } else if (tid < 80) {
        int r = tid - 64;
        B[B2S + r] = sb2[ck * 32 + 2 * r + PO];
        B[B2T + r] = tb2[ck * 32 + 2 * r + PO];
    } else if (tid < 112) {
        int q = tid - 80;               // 0..31: [act 16 | pas 16]
        int dim = (q < 16) ? (2 * q + A) : (2 * (q - 16) + PO);
        float a = anS[ck * 32 + dim];
        float t = anT[ck * 32 + dim];
        float e = __expf(-a);
        B[ANE + q] = e;
        B[ANF + q] = -t * e;
    } else if (tid == 112) {
        float s = 0.f;
        for (int d = 0; d < 32; d++) s += anS[ck * 32 + d];
        B[ASUM] = s;
    }
}

// ---------- one inverse layer: quarter-split hidden, 1 node/thread ----------
DEV_INLINE void layer_compute(const float* __restrict__ sb, int q,
                              ull (&a)[8], ull (&p)[8], float& ld)
{
    // ActNorm inverse (E/F stored in act|pas order)
    const ull* E = (const ull*)(sb + ANE);
    const ull* F = (const ull*)(sb + ANF);
    #pragma unroll
    for (int j = 0; j < 8; j++) {
        a[j] = ffma2(a[j], E[j],     F[j]);
        p[j] = ffma2(p[j], E[8 + j], F[8 + j]);
    }
    ld -= sb[ASUM];

    // 16 outputs as 8 packed pairs
    ull s[8], t[8];
    const ull* b2s = (const ull*)(sb + B2S);
    const ull* b2t = (const ull*)(sb + B2T);
    #pragma unroll
    for (int j = 0; j < 8; j++) {
        s[j] = (q == 0) ? b2s[j] : 0ULL;
        t[j] = (q == 0) ? b2t[j] : 0ULL;
    }

    #pragma unroll 4
    for (int il = 0; il < 16; il++) {
        const int gi = il * 4 + q;                // this thread's hidden unit
        const ulonglong2* r1s = (const ulonglong2*)(sb + W1S + gi * 20);
        const ulonglong2* r1t = (const ulonglong2*)(sb + W1T + gi * 20);
        ull as = pack2(sb[B1S + gi], 0.f);
        ull at = pack2(sb[B1T + gi], 0.f);
        #pragma unroll
        for (int ch = 0; ch < 4; ch++) {
            ulonglong2 ws = r1s[ch], wt = r1t[ch];
            as = ffma2(ws.x, a[2 * ch],     as);
            as = ffma2(ws.y, a[2 * ch + 1], as);
            at = ffma2(wt.x, a[2 * ch],     at);
            at = ffma2(wt.y, a[2 * ch + 1], at);
        }
        float x0, x1;
        unpack2(as, x0, x1); float hs = fmaxf(x0 + x1, 0.f);
        unpack2(at, x0, x1); float ht = fmaxf(x0 + x1, 0.f);
        ull hsp = pack2(hs, hs), htp = pack2(ht, ht);

        const ulonglong2* r2s = (const ulonglong2*)(sb + W2S + gi * 20);
        const ulonglong2* r2t = (const ulonglong2*)(sb + W2T + gi * 20);
        #pragma unroll
        for (int ch = 0; ch < 4; ch++) {
            ulonglong2 ws = r2s[ch], wt = r2t[ch];
            s[2 * ch]     = ffma2(ws.x, hsp, s[2 * ch]);
            s[2 * ch + 1] = ffma2(ws.y, hsp, s[2 * ch + 1]);
            t[2 * ch]     = ffma2(wt.x, htp, t[2 * ch]);
            t[2 * ch + 1] = ffma2(wt.y, htp, t[2 * ch + 1]);
        }
    }

    // butterfly over the 4 quarter-threads
    #pragma unroll
    for (int j = 0; j < 8; j++) {
        s[j] = add2(s[j], __shfl_xor_sync(0xffffffffu, s[j], 1));
        s[j] = add2(s[j], __shfl_xor_sync(0xffffffffu, s[j], 2));
        t[j] = add2(t[j], __shfl_xor_sync(0xffffffffu, t[j], 1));
        t[j] = add2(t[j], __shfl_xor_sync(0xffffffffu, t[j], 2));
    }

    // passive update + logdet (redundant across quarters, consistent)
    #pragma unroll
    for (int j = 0; j < 8; j++) {
        float sa, sbv;
        unpack2(s[j], sa, sbv);
        ld -= (sa + sbv);
        ull e2 = pack2(__expf(-sa), __expf(-sbv));
        p[j] = ffma2(p[j], e2, neg2(mul2(t[j], e2)));
    }
}

__global__ void __launch_bounds__(64, 7)
flow_kernel(const float* __restrict__ nodes,
            const float* __restrict__ loc, const float* __restrict__ lsc)
{
    __shared__ __align__(16) float sbuf[BLOB];   // single buffer: 22.5 KB
    const int tid  = threadIdx.x;
    const int q    = tid & 3;            // quarter of hidden units
    const int slot = tid >> 2;           // 0..15
    const int c    = blockIdx.y;
    const int node = blockIdx.x * 16 + slot;

    // z packed by parity: ze[j]=(dims 4j,4j+2), zo[j]=(4j+1,4j+3)
    ull ze[8], zo[8];
    {
        const float4* np = (const float4*)(nodes + (size_t)node * 32);
        #pragma unroll
        for (int j = 0; j < 8; j++) {
            float4 v = np[j];
            ze[j] = pack2(v.x, v.z); zo[j] = pack2(v.y, v.w);
        }
    }
    float ld = 0.f;

    const float* gb = g_blob + (size_t)(c * 64) * BLOB;

    stage(sbuf, gb + (size_t)63 * BLOB, tid);
    wait_stage();
    __syncthreads();

    #pragma unroll 1
    for (int k = 63; k > 0; k -= 2) {
        // layer k (odd): active = odd dims
        layer_compute(sbuf, q, zo, ze, ld);
        __syncthreads();
        stage(sbuf, gb + (size_t)(k - 1) * BLOB, tid);
        wait_stage();
        __syncthreads();
        // layer k-1 (even): active = even dims
        layer_compute(sbuf, q, ze, zo, ld);
        if (k >= 3) {
            __syncthreads();
            stage(sbuf, gb + (size_t)(k - 2) * BLOB, tid);
            wait_stage();
            __syncthreads();
        }
    }

    // DiagGaussian log_prob
    float acc = 0.f;
    const float* lp = loc + c * 32;
    const float* sp = lsc + c * 32;
    #pragma unroll
    for (int j = 0; j < 8; j++) {
        float e0, e1, o0, o1;
        unpack2(ze[j], e0, e1); unpack2(zo[j], o0, o1);
        float z4[4] = {e0, o0, e1, o1};
        #pragma unroll
        for (int b = 0; b < 4; b++) {
            int d = 4 * j + b;
            float ls = __ldg(sp + d);
            float u  = (z4[b] - __ldg(lp + d)) * __expf(-ls);
            acc += ls + 0.5f * u * u;
        }
    }
    if (q == 0)
        g_Bm[c * NN + node] = __expf(ld - 29.406037829f - acc);
}

// Fold L1 row-normalizers and softmax-normalized S into one 8x8 matrix.
__global__ void norm_kernel(const float* __restrict__ S_unc)
{
    __shared__ float sh_r[8];
    __shared__ float sh_e[64];
    const int tid = threadIdx.x;
    const int w = tid >> 5, lane = tid & 31;

    float s = 0.f;
    for (int i = lane; i < NN; i += 32) s += g_Bm[w * NN + i];
    #pragma unroll
    for (int o = 16; o; o >>= 1) s += __shfl_xor_sync(0xffffffffu, s, o);
    if (lane == 0) sh_r[w] = fmaxf(s, 1e-12f);
    if (tid < 64) sh_e[tid] = expf(S_unc[tid]);
    __syncthreads();
    if (tid < 64) {
        float tot = 0.f;
        #pragma unroll
        for (int i = 0; i < 64; i++) tot += sh_e[i];
        int c1 = tid >> 3, c2 = tid & 7;
        g_Sn[tid] = sh_e[tid] / (tot * sh_r[c1] * sh_r[c2]);
    }
}

__global__ void __launch_bounds__(256)
out_kernel(float* __restrict__ out)
{
    __shared__ float B1[8][64];
    __shared__ float B2[8][64];
    __shared__ float T2[8][64];
    const int tid = threadIdx.x;
    const int n10 = blockIdx.y * 64;
    const int n20 = blockIdx.x * 64;

    for (int t = tid; t < 512; t += 256) {
        int cc = t >> 6, j = t & 63;
        B1[cc][j] = g_Bm[cc * NN + n10 + j];
        B2[cc][j] = g_Bm[cc * NN + n20 + j];
    }
    __syncthreads();
    if (tid < 64) {
        #pragma unroll
        for (int c1 = 0; c1 < 8; c1++) {
            float a = 0.f;
            #pragma unroll
            for (int c2 = 0; c2 < 8; c2++)
                a = fmaf(g_Sn[c1 * 8 + c2], B2[c2][tid], a);
            T2[c1][tid] = a;
        }
    }
    __syncthreads();

    const int ty = tid >> 4, tx = tid & 15;
    float bv[4][8], tv[8][4];
    #pragma unroll
    for (int cc = 0; cc < 8; cc++) {
        #pragma unroll
        for (int p = 0; p < 4; p++) {
            bv[p][cc] = B1[cc][ty * 4 + p];
            tv[cc][p] = T2[cc][tx * 4 + p];
        }
    }
    #pragma unroll
    for (int p = 0; p < 4; p++) {
        float4 o = {0.f, 0.f, 0.f, 0.f};
        #pragma unroll
        for (int cc = 0; cc < 8; cc++) {
            o.x = fmaf(bv[p][cc], tv[cc][0], o.x);
            o.y = fmaf(bv[p][cc], tv[cc][1], o.y);
            o.z = fmaf(bv[p][cc], tv[cc][2], o.z);
            o.w = fmaf(bv[p][cc], tv[cc][3], o.w);
        }
        *((float4*)(out + (size_t)(n10 + ty * 4 + p) * NN + n20 + tx * 4)) = o;
    }
}

extern "C" void kernel_launch(void* const* d_in, const int* in_sizes, int n_in,
                              void* d_out, int out_size)
{
    const float* nodes = (const float*)d_in[0];
    const float* sW1   = (const float*)d_in[1];
    const float* sb1   = (const float*)d_in[2];
    const float* sW2   = (const float*)d_in[3];
    const float* sb2   = (const float*)d_in[4];
    const float* tW1   = (const float*)d_in[5];
    const float* tb1   = (const float*)d_in[6];
    const float* tW2   = (const float*)d_in[7];
    const float* tb2   = (const float*)d_in[8];
    const float* anS   = (const float*)d_in[9];
    const float* anT   = (const float*)d_in[10];
    const float* loc   = (const float*)d_in[11];
    const float* lsc   = (const float*)d_in[12];
    const float* S_unc = (const float*)d_in[13];
    float* out = (float*)d_out;

    repack_kernel<<<C * K, 128>>>(sW1, sb1, sW2, sb2, tW1, tb1, tW2, tb2, anS, anT);
    dim3 fg(NN / 16, C);                 // 128 x 8 = 1024 blocks, 64 thr, npt=1
    flow_kernel<<<fg, 64>>>(nodes, loc, lsc);
    norm_kernel<<<1, 256>>>(S_unc);
    dim3 og(NN / 64, NN / 64);
    out_kernel<<<og, 256>>>(out);
}

// round 12
// speedup vs baseline: 1.6806x; 1.6806x over previous
#include <cuda_runtime.h>

#define DEV_INLINE __device__ __forceinline__
typedef unsigned long long ull;

constexpr int C  = 8;
constexpr int K  = 64;
constexpr int NN = 2048;

// ---- per-(c,k) repacked blob layout (floats) ----
// s/t weight banks are padded 16 floats (=16 banks) apart so that within one
// warp instruction the s-lanes and t-lanes hit disjoint bank sets.
constexpr int BLOB = 5632;               // 22528 B = 1408 x 16B chunks; /64 thr = 22
constexpr int W1S = 0;                   // [64][20] stride-padded, cols 0..15 valid
constexpr int W1T = 1296;                // = W1S + 1280 + 16 (bank shift)
constexpr int W2S = 2592;                // transposed [i][r], stride 20
constexpr int W2T = 3888;                // = W2S + 1280 + 16
constexpr int B1S = 5168, B1T = 5236;    // δ68 ≡ 4 mod 32 banks
constexpr int B2S = 5300, B2T = 5316;    // passive order
constexpr int ANE = 5332;                // [act 16 | pas 16] exp(-s)
constexpr int ANF = 5364;                // [act 16 | pas 16] -t*exp(-s)
constexpr int ASUM = 5396;

__device__ float g_blob[C * K * BLOB];
__device__ float g_Bm[C * NN];
__device__ float g_Sn[C * C];

// ---------- packed f32x2 helpers ----------
DEV_INLINE ull pack2(float lo, float hi) {
    ull r; asm("mov.b64 %0, {%1,%2};" : "=l"(r) : "f"(lo), "f"(hi)); return r;
}
DEV_INLINE void unpack2(ull v, float& lo, float& hi) {
    asm("mov.b64 {%0,%1}, %2;" : "=f"(lo), "=f"(hi) : "l"(v));
}
DEV_INLINE ull ffma2(ull a, ull b, ull c) {
    ull d; asm("fma.rn.f32x2 %0, %1, %2, %3;" : "=l"(d) : "l"(a), "l"(b), "l"(c)); return d;
}
DEV_INLINE ull add2(ull a, ull b) {
    ull d; asm("add.rn.f32x2 %0, %1, %2;" : "=l"(d) : "l"(a), "l"(b)); return d;
}
DEV_INLINE ull mul2(ull a, ull b) {
    ull d; asm("mul.rn.f32x2 %0, %1, %2;" : "=l"(d) : "l"(a), "l"(b)); return d;
}
DEV_INLINE ull neg2(ull a) { return a ^ 0x8000000080000000ULL; }

// ---------- cp.async staging (64-thread block: 22 chunks each) ----------
DEV_INLINE void stage(float* sdst, const float* gsrc, int tid) {
    unsigned sa = (unsigned)__cvta_generic_to_shared(sdst);
    #pragma unroll
    for (int i = 0; i < 22; i++) {
        int ch = tid + i * 64;
        asm volatile("cp.async.cg.shared.global [%0], [%1], 16;"
                     :: "r"(sa + ch * 16), "l"(gsrc + ch * 4));
    }
    asm volatile("cp.async.commit_group;");
}
DEV_INLINE void wait_stage() {
    asm volatile("cp.async.wait_group 0;" ::: "memory");
}

// ---------- repack: gather/compact/transpose weights once ----------
__global__ void __launch_bounds__(128)
repack_kernel(const float* __restrict__ sW1, const float* __restrict__ sb1,
              const float* __restrict__ sW2, const float* __restrict__ sb2,
              const float* __restrict__ tW1, const float* __restrict__ tb1,
              const float* __restrict__ tW2, const float* __restrict__ tb2,
              const float* __restrict__ anS, const float* __restrict__ anT)
{
    const int ck = blockIdx.x;          // c*64+k
    const int k = ck & 63;
    const int A = k & 1, PO = 1 - A;    // active / passive parity
    float* B = g_blob + (size_t)ck * BLOB;
    const int tid = threadIdx.x;
    const size_t wo = (size_t)ck * 2048;

    for (int idx = tid; idx < 1024; idx += 128) {
        int i = idx >> 4, j = idx & 15;
        B[W1S + i * 20 + j] = sW1[wo + i * 32 + 2 * j + A];
        B[W1T + i * 20 + j] = tW1[wo + i * 32 + 2 * j + A];
        B[W2S + i * 20 + j] = sW2[wo + (2 * j + PO) * 64 + i];
        B[W2T + i * 20 + j] = tW2[wo + (2 * j + PO) * 64 + i];
    }
    if (tid < 64) {
        B[B1S + tid] = sb1[ck * 64 + tid];
        B[B1T + tid] = tb1[ck * 64 + tid];
    } else if (tid < 80) {
        int r = tid - 64;
        B[B2S + r] = sb2[ck * 32 + 2 * r + PO];
        B[B2T + r] = tb2[ck * 32 + 2 * r + PO];
    } else if (tid < 112) {
        int q = tid - 80;               // 0..31: [act 16 | pas 16]
        int dim = (q < 16) ? (2 * q + A) : (2 * (q - 16) + PO);
        float a = anS[ck * 32 + dim];
        float t = anT[ck * 32 + dim];
        float e = __expf(-a);
        B[ANE + q] = e;
        B[ANF + q] = -t * e;
    } else if (tid == 112) {
        float s = 0.f;
        for (int d = 0; d < 32; d++) s += anS[ck * 32 + d];
        B[ASUM] = s;
    }
}

// ---------- one inverse layer ----------
// 8 threads per 4-node group: q = hidden quarter (tid&3), m = mlp (0=s,1=t).
// Each thread: 4 nodes, one MLP, 16 hidden units. Butterfly over q, exchange
// e^{-s} <-> t over m. Per-node log-dets.
DEV_INLINE void layer_compute(const float* __restrict__ sb, int q, int m,
                              ull (&a)[4][8], ull (&p)[4][8], float (&ld)[4])
{
    // ActNorm inverse (E/F stored in act|pas order) — all threads, all nodes
    const ull* E = (const ull*)(sb + ANE);
    const ull* F = (const ull*)(sb + ANF);
    #pragma unroll
    for (int j = 0; j < 8; j++) {
        ull e = E[j], f = F[j];
        ull e2 = E[8 + j], f2 = F[8 + j];
        #pragma unroll
        for (int n = 0; n < 4; n++) {
            a[n][j] = ffma2(a[n][j], e, f);
            p[n][j] = ffma2(p[n][j], e2, f2);
        }
    }
    float asum = sb[ASUM];
    #pragma unroll
    for (int n = 0; n < 4; n++) ld[n] -= asum;

    // this thread's MLP weight banks (s/t bank-shifted by 16)
    const float* w1 = sb + (m ? W1T : W1S);
    const float* w2 = sb + (m ? W2T : W2S);
    const float* b1 = sb + (m ? B1T : B1S);
    const ull*   b2 = (const ull*)(sb + (m ? B2T : B2S));

    // 16 outputs as 8 packed pairs, per node
    ull acc[4][8];
    #pragma unroll
    for (int j = 0; j < 8; j++) {
        ull b = (q == 0) ? b2[j] : 0ULL;
        #pragma unroll
        for (int n = 0; n < 4; n++) acc[n][j] = b;
    }

    #pragma unroll 2
    for (int il = 0; il < 16; il++) {
        const int gi = il * 4 + q;                  // this thread's hidden unit
        const ulonglong2* r1 = (const ulonglong2*)(w1 + gi * 20);
        float b1v = b1[gi];
        ull h[4];
        #pragma unroll
        for (int n = 0; n < 4; n++) h[n] = pack2(b1v, 0.f);
        #pragma unroll
        for (int ch = 0; ch < 2; ch++) {
            ulonglong2 wa = r1[2 * ch], wb = r1[2 * ch + 1];
            #pragma unroll
            for (int n = 0; n < 4; n++) {
                h[n] = ffma2(wa.x, a[n][4 * ch],     h[n]);
                h[n] = ffma2(wa.y, a[n][4 * ch + 1], h[n]);
                h[n] = ffma2(wb.x, a[n][4 * ch + 2], h[n]);
                h[n] = ffma2(wb.y, a[n][4 * ch + 3], h[n]);
            }
        }
        ull hp[4];
        #pragma unroll
        for (int n = 0; n < 4; n++) {
            float x0, x1; unpack2(h[n], x0, x1);
            float hv = fmaxf(x0 + x1, 0.f);
            hp[n] = pack2(hv, hv);
        }
        const ulonglong2* r2 = (const ulonglong2*)(w2 + gi * 20);
        #pragma unroll
        for (int ch = 0; ch < 4; ch++) {
            ulonglong2 w = r2[ch];
            #pragma unroll
            for (int n = 0; n < 4; n++) {
                acc[n][2 * ch]     = ffma2(w.x, hp[n], acc[n][2 * ch]);
                acc[n][2 * ch + 1] = ffma2(w.y, hp[n], acc[n][2 * ch + 1]);
            }
        }
    }

    // butterfly over q (xor 1,2), then exchange e^{-s} <-> t over m (xor 4);
    // both m-lanes apply the identical passive update.
    #pragma unroll
    for (int j = 0; j < 8; j++) {
        #pragma unroll
        for (int n = 0; n < 4; n++) {
            ull v = acc[n][j];
            v = add2(v, __shfl_xor_sync(0xffffffffu, v, 1));
            v = add2(v, __shfl_xor_sync(0xffffffffu, v, 2));
            float x0, x1; unpack2(v, x0, x1);
            ull e2o = pack2(__expf(-x0), __expf(-x1));    // valid on m==0
            if (m == 0) ld[n] -= (x0 + x1);
            ull send = (m == 0) ? e2o : v;
            ull recv = __shfl_xor_sync(0xffffffffu, send, 4);
            ull e2v  = (m == 0) ? e2o : recv;
            ull tv   = (m == 0) ? recv : v;
            p[n][j] = ffma2(p[n][j], e2v, neg2(mul2(tv, e2v)));
        }
    }
}

__global__ void __launch_bounds__(64)
flow_kernel(const float* __restrict__ nodes,
            const float* __restrict__ loc, const float* __restrict__ lsc)
{
    __shared__ __align__(16) float sbuf[2][BLOB];
    const int tid  = threadIdx.x;
    const int q    = tid & 3;            // hidden quarter
    const int m    = (tid >> 2) & 1;     // 0 = s-MLP, 1 = t-MLP
    const int slot = tid >> 3;           // 0..7
    const int c    = blockIdx.y;
    const int nb   = blockIdx.x * 32 + slot;   // nodes nb, nb+8, nb+16, nb+24

    // z packed by parity: ze[j]=(dims 4j,4j+2), zo[j]=(4j+1,4j+3)
    ull ze[4][8], zo[4][8];
    #pragma unroll
    for (int n = 0; n < 4; n++) {
        const float4* np = (const float4*)(nodes + (size_t)(nb + 8 * n) * 32);
        #pragma unroll
        for (int j = 0; j < 8; j++) {
            float4 v = np[j];
            ze[n][j] = pack2(v.x, v.z); zo[n][j] = pack2(v.y, v.w);
        }
    }
    float ld[4] = {0.f, 0.f, 0.f, 0.f};

    const float* gb = g_blob + (size_t)(c * 64) * BLOB;

    stage(sbuf[0], gb + (size_t)63 * BLOB, tid);
    wait_stage();
    __syncthreads();

    #pragma unroll 1
    for (int k = 63; k > 0; k -= 2) {
        stage(sbuf[1], gb + (size_t)(k - 1) * BLOB, tid);
        // layer k (odd): active = odd dims
        layer_compute(sbuf[0], q, m, zo, ze, ld);
        wait_stage();
        __syncthreads();
        if (k >= 3) stage(sbuf[0], gb + (size_t)(k - 2) * BLOB, tid);
        // layer k-1 (even): active = even dims
        layer_compute(sbuf[1], q, m, ze, zo, ld);
        wait_stage();
        __syncthreads();
    }

    // DiagGaussian log_prob (redundant; written by q==0 && m==0)
    const float* lp = loc + c * 32;
    const float* sp = lsc + c * 32;
    #pragma unroll
    for (int n = 0; n < 4; n++) {
        float acc = 0.f;
        #pragma unroll
        for (int j = 0; j < 8; j++) {
            float e0, e1, o0, o1;
            unpack2(ze[n][j], e0, e1); unpack2(zo[n][j], o0, o1);
            float z4[4] = {e0, o0, e1, o1};
            #pragma unroll
            for (int b = 0; b < 4; b++) {
                int d = 4 * j + b;
                float ls = __ldg(sp + d);
                float u  = (z4[b] - __ldg(lp + d)) * __expf(-ls);
                acc += ls + 0.5f * u * u;
            }
        }
        if (q == 0 && m == 0)
            g_Bm[c * NN + nb + 8 * n] = __expf(ld[n] - 29.406037829f - acc);
    }
}

// Fold L1 row-normalizers and softmax-normalized S into one 8x8 matrix.
__global__ void norm_kernel(const float* __restrict__ S_unc)
{
    __shared__ float sh_r[8];
    __shared__ float sh_e[64];
    const int tid = threadIdx.x;
    const int w = tid >> 5, lane = tid & 31;

    float s = 0.f;
    for (int i = lane; i < NN; i += 32) s += g_Bm[w * NN + i];
    #pragma unroll
    for (int o = 16; o; o >>= 1) s += __shfl_xor_sync(0xffffffffu, s, o);
    if (lane == 0) sh_r[w] = fmaxf(s, 1e-12f);
    if (tid < 64) sh_e[tid] = expf(S_unc[tid]);
    __syncthreads();
    if (tid < 64) {
        float tot = 0.f;
        #pragma unroll
        for (int i = 0; i < 64; i++) tot += sh_e[i];
        int c1 = tid >> 3, c2 = tid & 7;
        g_Sn[tid] = sh_e[tid] / (tot * sh_r[c1] * sh_r[c2]);
    }
}

__global__ void __launch_bounds__(256)
out_kernel(float* __restrict__ out)
{
    __shared__ float B1[8][64];
    __shared__ float B2[8][64];
    __shared__ float T2[8][64];
    const int tid = threadIdx.x;
    const int n10 = blockIdx.y * 64;
    const int n20 = blockIdx.x * 64;

    for (int t = tid; t < 512; t += 256) {
        int cc = t >> 6, j = t & 63;
        B1[cc][j] = g_Bm[cc * NN + n10 + j];
        B2[cc][j] = g_Bm[cc * NN + n20 + j];
    }
    __syncthreads();
    if (tid < 64) {
        #pragma unroll
        for (int c1 = 0; c1 < 8; c1++) {
            float a = 0.f;
            #pragma unroll
            for (int c2 = 0; c2 < 8; c2++)
                a = fmaf(g_Sn[c1 * 8 + c2], B2[c2][tid], a);
            T2[c1][tid] = a;
        }
    }
    __syncthreads();

    const int ty = tid >> 4, tx = tid & 15;
    float bv[4][8], tv[8][4];
    #pragma unroll
    for (int cc = 0; cc < 8; cc++) {
        #pragma unroll
        for (int p = 0; p < 4; p++) {
            bv[p][cc] = B1[cc][ty * 4 + p];
            tv[cc][p] = T2[cc][tx * 4 + p];
        }
    }
    #pragma unroll
    for (int p = 0; p < 4; p++) {
        float4 o = {0.f, 0.f, 0.f, 0.f};
        #pragma unroll
        for (int cc = 0; cc < 8; cc++) {
            o.x = fmaf(bv[p][cc], tv[cc][0], o.x);
            o.y = fmaf(bv[p][cc], tv[cc][1], o.y);
            o.z = fmaf(bv[p][cc], tv[cc][2], o.z);
            o.w = fmaf(bv[p][cc], tv[cc][3], o.w);
        }
        *((float4*)(out + (size_t)(n10 + ty * 4 + p) * NN + n20 + tx * 4)) = o;
    }
}

extern "C" void kernel_launch(void* const* d_in, const int* in_sizes, int n_in,
                              void* d_out, int out_size)
{
    const float* nodes = (const float*)d_in[0];
    const float* sW1   = (const float*)d_in[1];
    const float* sb1   = (const float*)d_in[2];
    const float* sW2   = (const float*)d_in[3];
    const float* sb2   = (const float*)d_in[4];
    const float* tW1   = (const float*)d_in[5];
    const float* tb1   = (const float*)d_in[6];
    const float* tW2   = (const float*)d_in[7];
    const float* tb2   = (const float*)d_in[8];
    const float* anS   = (const float*)d_in[9];
    const float* anT   = (const float*)d_in[10];
    const float* loc   = (const float*)d_in[11];
    const float* lsc   = (const float*)d_in[12];
    const float* S_unc = (const float*)d_in[13];
    float* out = (float*)d_out;

    repack_kernel<<<C * K, 128>>>(sW1, sb1, sW2, sb2, tW1, tb1, tW2, tb2, anS, anT);
    dim3 fg(NN / 32, C);                 // 64 x 8 = 512 blocks, 64 thr, npt=4
    flow_kernel<<<fg, 64>>>(nodes, loc, lsc);
    norm_kernel<<<1, 256>>>(S_unc);
    dim3 og(NN / 64, NN / 64);
    out_kernel<<<og, 256>>>(out);
}